// round 2
// baseline (speedup 1.0000x reference)
#include <cuda_runtime.h>
#include <cstdint>

// GraphAttentionLayer: N=12288, IN_F=256, OUT_F=128, slope=0.2
// out = [h_prime (N x 128) | attention (N x N)] fp32, tuple order.
//
// Pipeline:
//  k_ht     : h_t = h @ W                      -> g_ht
//  k_srctgt : src/tgt dots + exp tables        -> g_Es,g_Es2,g_Etgt,g_Etgt2
//  k_l      : row softmax denominators, fold   -> g_A = Es/l, g_B = Es2/l
//  k_main   : fused attention write + h_prime GEMM (packed fp32x2 FMA)
//
// Identity used: exp(leaky(s)) = max(exp(s), exp(0.2 s)) since leaky(s)=max(s,0.2s)
// and exp(s) = exp(src_i)*exp(tgt_j) factorizes. Scores are O(10) so no
// max-subtraction is needed (no overflow; matches ref within fp32 rounding).

#define KN    12288
#define INF_  256
#define OUTF  128

__device__ float g_ht[(size_t)KN * OUTF];
__device__ float g_Es[KN], g_Es2[KN], g_Etgt[KN], g_Etgt2[KN];
__device__ float g_A[KN], g_B[KN];

// packed fp32x2 fma (Blackwell sm_103a)
#define FMA_F32X2(d, a, b, c) \
    asm("fma.rn.f32x2 %0, %1, %2, %3;" : "=l"(d) : "l"(a), "l"(b), "l"(c))

// ---------------- K1: h_t = h @ W ----------------
__global__ void __launch_bounds__(256) k_ht(const float* __restrict__ h,
                                            const float* __restrict__ W) {
    __shared__ float h_s[8 * INF_];
    int t = threadIdx.x;
    int r0 = blockIdx.x * 8;
    for (int idx = t; idx < 8 * INF_; idx += 256)
        h_s[idx] = h[(size_t)r0 * INF_ + idx];
    __syncthreads();

    int c  = t & 127;   // output col
    int rg = t >> 7;    // 0..1 row-group (4 rows each)
    float acc[4] = {0.f, 0.f, 0.f, 0.f};
    for (int k = 0; k < INF_; k++) {
        float w = W[k * OUTF + c];
#pragma unroll
        for (int rr = 0; rr < 4; rr++)
            acc[rr] = fmaf(h_s[(rg * 4 + rr) * INF_ + k], w, acc[rr]);
    }
#pragma unroll
    for (int rr = 0; rr < 4; rr++)
        g_ht[(size_t)(r0 + rg * 4 + rr) * OUTF + c] = acc[rr];
}

// ---------------- K1b: src/tgt + exp tables ----------------
__global__ void __launch_bounds__(128) k_srctgt(const float* __restrict__ a) {
    int r = blockIdx.x;
    int t = threadIdx.x;  // 128 threads
    float v  = g_ht[(size_t)r * OUTF + t];
    float s1 = v * a[t];          // src contribution
    float s2 = v * a[OUTF + t];   // tgt contribution
#pragma unroll
    for (int o = 16; o > 0; o >>= 1) {
        s1 += __shfl_down_sync(0xFFFFFFFFu, s1, o);
        s2 += __shfl_down_sync(0xFFFFFFFFu, s2, o);
    }
    __shared__ float red[8];
    int w = t >> 5, l = t & 31;
    if (l == 0) { red[w] = s1; red[4 + w] = s2; }
    __syncthreads();
    if (t == 0) {
        float src = red[0] + red[1] + red[2] + red[3];
        float tgt = red[4] + red[5] + red[6] + red[7];
        g_Es[r]    = expf(src);
        g_Es2[r]   = expf(0.2f * src);
        g_Etgt[r]  = expf(tgt);
        g_Etgt2[r] = expf(0.2f * tgt);
    }
}

// ---------------- Kl: row denominators ----------------
__global__ void __launch_bounds__(256) k_l(const int* __restrict__ adj) {
    int w = threadIdx.x >> 5, l = threadIdx.x & 31;
    int r = blockIdx.x * 8 + w;
    float Es = g_Es[r], Es2 = g_Es2[r];
    const int4* arow = (const int4*)(adj + (size_t)r * KN);
    const float4* E1 = (const float4*)g_Etgt;
    const float4* E2 = (const float4*)g_Etgt2;
    float lsum = 0.f;
#pragma unroll 2
    for (int q = l; q < KN / 4; q += 32) {
        int4 m = arow[q];
        float4 e1 = E1[q];
        float4 e2 = E2[q];
        if (m.x) lsum += fmaxf(Es * e1.x, Es2 * e2.x);
        if (m.y) lsum += fmaxf(Es * e1.y, Es2 * e2.y);
        if (m.z) lsum += fmaxf(Es * e1.z, Es2 * e2.z);
        if (m.w) lsum += fmaxf(Es * e1.w, Es2 * e2.w);
    }
#pragma unroll
    for (int o = 16; o > 0; o >>= 1) lsum += __shfl_down_sync(0xFFFFFFFFu, lsum, o);
    if (l == 0) {
        float inv = 1.0f / lsum;
        g_A[r] = Es * inv;
        g_B[r] = Es2 * inv;
    }
}

// ---------------- K2: fused attention + h_prime GEMM ----------------
// Block: 32 rows x 128 dims, loops j in chunks of 32.
__global__ void __launch_bounds__(256) k_main(const int* __restrict__ adj,
                                              float* __restrict__ out) {
    __shared__ float ht_s[32][132];                     // +4 pad (conflict-free)
    __shared__ __align__(16) float2 p_s[32][34];        // duplicated p, 16B-aligned rows
    __shared__ float A_s[32], B_s[32];

    int t  = threadIdx.x;
    int i0 = blockIdx.x * 32;
    if (t < 32) { A_s[t] = g_A[i0 + t]; B_s[t] = g_B[i0 + t]; }
    __syncthreads();

    unsigned long long acc[8];
#pragma unroll
    for (int k = 0; k < 8; k++) acc[k] = 0ull;

    const int dp = t & 63;        // d-pair: covers dims 2dp, 2dp+1
    const int ig = t >> 6;        // i-group: rows ig*8 .. ig*8+7
    const int ii = t >> 3;        // phase-a row 0..31
    const int jb = (t & 7) << 2;  // phase-a j offset 0,4,...,28

    const float aA = A_s[ii], bB = B_s[ii];
    float* __restrict__ attn = out + (size_t)KN * OUTF;
    const size_t arow_base = (size_t)(i0 + ii) * KN + jb;

    for (int j0 = 0; j0 < KN; j0 += 32) {
        // stage h_t chunk [32 x 128] (linear, conflict-free)
#pragma unroll
        for (int k = 0; k < 16; k++) {
            int lin = k * 256 + t;
            int row = lin >> 7, col = lin & 127;
            ht_s[row][col] = g_ht[(size_t)(j0 + row) * OUTF + col];
        }
        // compute final attention values for 32x32 tile; write out + stage duplicated
        {
            int4 m    = *(const int4*)(adj + arow_base + j0);
            float4 e1 = *(const float4*)(g_Etgt + j0 + jb);
            float4 e2 = *(const float4*)(g_Etgt2 + j0 + jb);
            float p0 = m.x ? fmaxf(aA * e1.x, bB * e2.x) : 0.f;
            float p1 = m.y ? fmaxf(aA * e1.y, bB * e2.y) : 0.f;
            float p2 = m.z ? fmaxf(aA * e1.z, bB * e2.z) : 0.f;
            float p3 = m.w ? fmaxf(aA * e1.w, bB * e2.w) : 0.f;
            *(float4*)(attn + arow_base + j0) = make_float4(p0, p1, p2, p3);
            p_s[jb + 0][ii] = make_float2(p0, p0);
            p_s[jb + 1][ii] = make_float2(p1, p1);
            p_s[jb + 2][ii] = make_float2(p2, p2);
            p_s[jb + 3][ii] = make_float2(p3, p3);
        }
        __syncthreads();

        // GEMM sub-loop: acc[i] += p[jj][i] * ht[jj][dp-pair], packed fp32x2
#pragma unroll 2
        for (int jj = 0; jj < 32; jj++) {
            unsigned long long ht2 = *(const unsigned long long*)(&ht_s[jj][dp * 2]);
            const ulonglong2* pp = (const ulonglong2*)(&p_s[jj][ig * 8]);
            ulonglong2 q0 = pp[0], q1 = pp[1], q2 = pp[2], q3 = pp[3];
            FMA_F32X2(acc[0], q0.x, ht2, acc[0]);
            FMA_F32X2(acc[1], q0.y, ht2, acc[1]);
            FMA_F32X2(acc[2], q1.x, ht2, acc[2]);
            FMA_F32X2(acc[3], q1.y, ht2, acc[3]);
            FMA_F32X2(acc[4], q2.x, ht2, acc[4]);
            FMA_F32X2(acc[5], q2.y, ht2, acc[5]);
            FMA_F32X2(acc[6], q3.x, ht2, acc[6]);
            FMA_F32X2(acc[7], q3.y, ht2, acc[7]);
        }
        __syncthreads();
    }

    // epilogue: h_prime
#pragma unroll
    for (int k = 0; k < 8; k++) {
        int i = i0 + ig * 8 + k;
        *(float2*)(out + (size_t)i * OUTF + dp * 2) = *(float2*)(&acc[k]);
    }
}

extern "C" void kernel_launch(void* const* d_in, const int* in_sizes, int n_in,
                              void* d_out, int out_size) {
    const float* h   = (const float*)d_in[0];
    const int*   adj = (const int*)d_in[1];
    const float* W   = (const float*)d_in[2];
    const float* a   = (const float*)d_in[3];
    float* out = (float*)d_out;

    k_ht<<<KN / 8, 256>>>(h, W);
    k_srctgt<<<KN, 128>>>(a);
    k_l<<<KN / 8, 256>>>(adj);
    k_main<<<KN / 32, 256>>>(adj, out);
}

// round 4
// speedup vs baseline: 2.7910x; 2.7910x over previous
#include <cuda_runtime.h>
#include <cuda_fp16.h>
#include <cstdint>

// GraphAttentionLayer: N=12288, IN_F=256, OUT_F=128, slope=0.2
// out = [h_prime (N x 128) | attention (N x N)] fp32.
//
//  k_ht     : h_t = h @ W
//  k_srctgt : src/tgt dots + exp tables (exp(leaky(s)) = max(Es*Et, Es2*Et2))
//  k_split  : h_t -> transposed fp16 hi/lo  (for MMA B operand)
//  k_bits   : adj -> packed bitmask + softmax row denominators (folded A,B)
//  k_main   : P fragments generated in registers (and stored as attention),
//             B via cp.async double-buffer + ldmatrix, mma.sync m16n8k16
//             f32<-f16 with 3-term hi/lo split (AhBh + AhBl + AlBh).

#define KN    12288
#define INF_  256
#define OUTF  128
#define NWORDS (KN / 32)     // 384
#define CH    128            // K-chunk
#define NC    (KN / CH)      // 96

__device__ float g_ht[(size_t)KN * OUTF];
__device__ __half g_htT_hi[(size_t)OUTF * KN];
__device__ __half g_htT_lo[(size_t)OUTF * KN];
__device__ __align__(16) float g_Es[KN], g_Es2[KN], g_Etgt[KN], g_Etgt2[KN];
__device__ float g_A[KN], g_B[KN];
__device__ __align__(16) uint32_t g_bits[(size_t)KN * NWORDS];

// ---------------- helpers ----------------
__device__ __forceinline__ uint32_t smem_u32(const void* p) {
    uint32_t a;
    asm("{ .reg .u64 t; cvta.to.shared.u64 t, %1; cvt.u32.u64 %0, t; }" : "=r"(a) : "l"(p));
    return a;
}
// pack two f32 -> f16x2 (p0 in low half)
__device__ __forceinline__ uint32_t packh2(float p0, float p1) {
    uint32_t r;
    asm("cvt.rn.f16x2.f32 %0, %1, %2;" : "=r"(r) : "f"(p1), "f"(p0));
    return r;
}
__device__ __forceinline__ float h2lo(uint32_t v) {
    return __half2float(__ushort_as_half((unsigned short)(v & 0xFFFFu)));
}
__device__ __forceinline__ float h2hi(uint32_t v) {
    return __half2float(__ushort_as_half((unsigned short)(v >> 16)));
}

#define MMA16816(d, a0, a1, a2, a3, b0, b1) \
    asm volatile( \
        "mma.sync.aligned.m16n8k16.row.col.f32.f16.f16.f32 " \
        "{%0,%1,%2,%3}, {%4,%5,%6,%7}, {%8,%9}, {%0,%1,%2,%3};" \
        : "+f"((d).x), "+f"((d).y), "+f"((d).z), "+f"((d).w) \
        : "r"(a0), "r"(a1), "r"(a2), "r"(a3), "r"(b0), "r"(b1))

#define LDMX4(r0, r1, r2, r3, ad) \
    asm volatile("ldmatrix.sync.aligned.m8n8.x4.shared.b16 {%0,%1,%2,%3}, [%4];" \
                 : "=r"(r0), "=r"(r1), "=r"(r2), "=r"(r3) : "r"(ad))

#define CP16(dst, src) \
    asm volatile("cp.async.cg.shared.global [%0], [%1], 16;" :: "r"(dst), "l"(src) : "memory")
#define CP_COMMIT() asm volatile("cp.async.commit_group;" ::: "memory")
#define CP_WAIT1()  asm volatile("cp.async.wait_group 1;" ::: "memory")
#define CP_WAIT0()  asm volatile("cp.async.wait_group 0;" ::: "memory")

// ---------------- K1: h_t = h @ W ----------------
__global__ void __launch_bounds__(256) k_ht(const float* __restrict__ h,
                                            const float* __restrict__ W) {
    __shared__ float h_s[8 * INF_];
    int t = threadIdx.x;
    int r0 = blockIdx.x * 8;
    for (int idx = t; idx < 8 * INF_; idx += 256)
        h_s[idx] = h[(size_t)r0 * INF_ + idx];
    __syncthreads();
    int c  = t & 127;
    int rg = t >> 7;
    float acc[4] = {0.f, 0.f, 0.f, 0.f};
    for (int k = 0; k < INF_; k++) {
        float w = W[k * OUTF + c];
#pragma unroll
        for (int rr = 0; rr < 4; rr++)
            acc[rr] = fmaf(h_s[(rg * 4 + rr) * INF_ + k], w, acc[rr]);
    }
#pragma unroll
    for (int rr = 0; rr < 4; rr++)
        g_ht[(size_t)(r0 + rg * 4 + rr) * OUTF + c] = acc[rr];
}

// ---------------- K1b: src/tgt + exp tables ----------------
__global__ void __launch_bounds__(128) k_srctgt(const float* __restrict__ a) {
    int r = blockIdx.x;
    int t = threadIdx.x;
    float v  = g_ht[(size_t)r * OUTF + t];
    float s1 = v * a[t];
    float s2 = v * a[OUTF + t];
#pragma unroll
    for (int o = 16; o > 0; o >>= 1) {
        s1 += __shfl_down_sync(0xFFFFFFFFu, s1, o);
        s2 += __shfl_down_sync(0xFFFFFFFFu, s2, o);
    }
    __shared__ float red[8];
    int w = t >> 5, l = t & 31;
    if (l == 0) { red[w] = s1; red[4 + w] = s2; }
    __syncthreads();
    if (t == 0) {
        float src = red[0] + red[1] + red[2] + red[3];
        float tgt = red[4] + red[5] + red[6] + red[7];
        g_Es[r]    = expf(src);
        g_Es2[r]   = expf(0.2f * src);
        g_Etgt[r]  = expf(tgt);
        g_Etgt2[r] = expf(0.2f * tgt);
    }
}

// ---------------- K1c: transpose + fp16 hi/lo split ----------------
__global__ void __launch_bounds__(256) k_split() {
    __shared__ float sm[32][33];
    int t  = threadIdx.x;
    int tx = t & 31, ty = t >> 5;
    int j0 = blockIdx.x * 32;
    int c0 = blockIdx.y * 32;
#pragma unroll
    for (int q = 0; q < 4; q++)
        sm[ty + q * 8][tx] = g_ht[(size_t)(j0 + ty + q * 8) * OUTF + c0 + tx];
    __syncthreads();
#pragma unroll
    for (int q = 0; q < 4; q++) {
        int c = c0 + ty + q * 8;
        float v = sm[tx][ty + q * 8];
        __half hi = __float2half_rn(v);
        __half lo = __float2half_rn(v - __half2float(hi));
        size_t idx = (size_t)c * KN + j0 + tx;
        g_htT_hi[idx] = hi;
        g_htT_lo[idx] = lo;
    }
}

// ---------------- Kbits: bitmask + row denominators ----------------
__global__ void __launch_bounds__(256) k_bits(const int* __restrict__ adj) {
    int w = threadIdx.x >> 5, l = threadIdx.x & 31;
    int r = blockIdx.x * 8 + w;
    float Es = g_Es[r], Es2 = g_Es2[r];
    const int* arow = adj + (size_t)r * KN;
    uint32_t* brow = g_bits + (size_t)r * NWORDS;
    float lsum = 0.f;
#pragma unroll 4
    for (int wd = 0; wd < NWORDS; wd++) {
        int j = wd * 32 + l;
        int m = arow[j];
        unsigned bal = __ballot_sync(0xFFFFFFFFu, m != 0);
        if (m) lsum += fmaxf(Es * g_Etgt[j], Es2 * g_Etgt2[j]);
        if (l == 0) brow[wd] = bal;
    }
#pragma unroll
    for (int o = 16; o > 0; o >>= 1) lsum += __shfl_down_sync(0xFFFFFFFFu, lsum, o);
    if (l == 0) {
        float inv = 1.0f / lsum;
        g_A[r] = Es * inv;
        g_B[r] = Es2 * inv;
    }
}

// ---------------- K2: fused P-gen + mma.sync GEMM ----------------
// B smem layout: rows n = 0..127, row stride 272B (64 halves hi? no: 128 halves
// = 256B data + 16B pad). buf layout: [buf][hi|lo][row][k]
#define ROWSTRIDE 272
#define VERBYTES  (128 * ROWSTRIDE)   // 34816
#define BUFBYTES  (2 * VERBYTES)      // 69632
#define SMEM_MAIN (2 * BUFBYTES)      // 139264

__global__ void __launch_bounds__(256, 1) k_main(float* __restrict__ out) {
    extern __shared__ char sm[];
    const uint32_t smb = smem_u32(sm);
    const int t  = threadIdx.x;
    const int w  = t >> 5, l = t & 31;
    const int g  = l >> 2, tq = l & 3;
    const int i0 = blockIdx.x * 128;
    const int row0 = i0 + w * 16 + g;
    const int row1 = row0 + 8;

    const float aA0 = g_A[row0], bB0 = g_B[row0];
    const float aA1 = g_A[row1], bB1 = g_B[row1];
    float* __restrict__ attn0 = out + (size_t)KN * OUTF + (size_t)row0 * KN;
    float* __restrict__ attn1 = out + (size_t)KN * OUTF + (size_t)row1 * KN;
    const uint4* __restrict__ bits0 = (const uint4*)(g_bits + (size_t)row0 * NWORDS);
    const uint4* __restrict__ bits1 = (const uint4*)(g_bits + (size_t)row1 * NWORDS);

    // cp.async assignment: thread covers rows (t>>4)+16i, 16B-vec (t&15)
    const int cpr = t >> 4;
    const int cpk = t & 15;
    // ldmatrix lane addressing
    const uint32_t lmrow = ((l >> 4) & 1) * 8 + (l & 7);
    const uint32_t lmoff = lmrow * ROWSTRIDE + ((l >> 3) & 1) * 16;

    float4 acc[16];
#pragma unroll
    for (int i = 0; i < 16; i++) acc[i] = make_float4(0.f, 0.f, 0.f, 0.f);

    // prologue: chunk 0 -> buf 0
    {
#pragma unroll
        for (int i = 0; i < 8; i++) {
            int row = cpr + i * 16;
            uint32_t d = smb + row * ROWSTRIDE + cpk * 16;
            CP16(d,            g_htT_hi + (size_t)row * KN + cpk * 8);
            CP16(d + VERBYTES, g_htT_lo + (size_t)row * KN + cpk * 8);
        }
        CP_COMMIT();
    }

    for (int c = 0; c < NC; c++) {
        const int buf = c & 1;
        if (c + 1 < NC) {
            const int jn = (c + 1) * CH;
            const uint32_t dstb = smb + (buf ^ 1) * BUFBYTES;
#pragma unroll
            for (int i = 0; i < 8; i++) {
                int row = cpr + i * 16;
                uint32_t d = dstb + row * ROWSTRIDE + cpk * 16;
                CP16(d,            g_htT_hi + (size_t)row * KN + jn + cpk * 8);
                CP16(d + VERBYTES, g_htT_lo + (size_t)row * KN + jn + cpk * 8);
            }
            CP_COMMIT();
            CP_WAIT1();
        } else {
            CP_WAIT0();
        }
        __syncthreads();

        const uint4 w0 = bits0[c];
        const uint4 w1 = bits1[c];
        const uint32_t lmb = smb + buf * BUFBYTES + lmoff;

#pragma unroll 2
        for (int kk = 0; kk < 8; kk++) {
            const int j = c * CH + kk * 16;
            float2 e1a = *(const float2*)(g_Etgt  + j + 2 * tq);
            float2 e1b = *(const float2*)(g_Etgt  + j + 2 * tq + 8);
            float2 e2a = *(const float2*)(g_Etgt2 + j + 2 * tq);
            float2 e2b = *(const float2*)(g_Etgt2 + j + 2 * tq + 8);
            const uint32_t bwa = ((const uint32_t*)&w0)[kk >> 1] >> ((kk & 1) * 16);
            const uint32_t bwb = ((const uint32_t*)&w1)[kk >> 1] >> ((kk & 1) * 16);

            float p00 = (bwa >> (2 * tq))     & 1 ? fmaxf(aA0 * e1a.x, bB0 * e2a.x) : 0.f;
            float p01 = (bwa >> (2 * tq + 1)) & 1 ? fmaxf(aA0 * e1a.y, bB0 * e2a.y) : 0.f;
            float p02 = (bwa >> (2 * tq + 8)) & 1 ? fmaxf(aA0 * e1b.x, bB0 * e2b.x) : 0.f;
            float p03 = (bwa >> (2 * tq + 9)) & 1 ? fmaxf(aA0 * e1b.y, bB0 * e2b.y) : 0.f;
            float p10 = (bwb >> (2 * tq))     & 1 ? fmaxf(aA1 * e1a.x, bB1 * e2a.x) : 0.f;
            float p11 = (bwb >> (2 * tq + 1)) & 1 ? fmaxf(aA1 * e1a.y, bB1 * e2a.y) : 0.f;
            float p12 = (bwb >> (2 * tq + 8)) & 1 ? fmaxf(aA1 * e1b.x, bB1 * e2b.x) : 0.f;
            float p13 = (bwb >> (2 * tq + 9)) & 1 ? fmaxf(aA1 * e1b.y, bB1 * e2b.y) : 0.f;

            *(float2*)(attn0 + j + 2 * tq)     = make_float2(p00, p01);
            *(float2*)(attn0 + j + 2 * tq + 8) = make_float2(p02, p03);
            *(float2*)(attn1 + j + 2 * tq)     = make_float2(p10, p11);
            *(float2*)(attn1 + j + 2 * tq + 8) = make_float2(p12, p13);

            // A fragments: a0=(g,k2t) a1=(g+8,k2t) a2=(g,k2t+8) a3=(g+8,k2t+8)
            const uint32_t ah0 = packh2(p00, p01);
            const uint32_t ah1 = packh2(p10, p11);
            const uint32_t ah2 = packh2(p02, p03);
            const uint32_t ah3 = packh2(p12, p13);
            const uint32_t al0 = packh2(p00 - h2lo(ah0), p01 - h2hi(ah0));
            const uint32_t al1 = packh2(p10 - h2lo(ah1), p11 - h2hi(ah1));
            const uint32_t al2 = packh2(p02 - h2lo(ah2), p03 - h2hi(ah2));
            const uint32_t al3 = packh2(p12 - h2lo(ah3), p13 - h2hi(ah3));

            const uint32_t lmk = lmb + kk * 32;
#pragma unroll
            for (int np = 0; np < 8; np++) {
                const uint32_t ad = lmk + np * (16 * ROWSTRIDE);
                uint32_t bh0, bh1, bh2, bh3, bl0, bl1, bl2, bl3;
                LDMX4(bh0, bh1, bh2, bh3, ad);
                LDMX4(bl0, bl1, bl2, bl3, ad + VERBYTES);
                MMA16816(acc[2 * np],     ah0, ah1, ah2, ah3, bh0, bh1);
                MMA16816(acc[2 * np + 1], ah0, ah1, ah2, ah3, bh2, bh3);
                MMA16816(acc[2 * np],     ah0, ah1, ah2, ah3, bl0, bl1);
                MMA16816(acc[2 * np + 1], ah0, ah1, ah2, ah3, bl2, bl3);
                MMA16816(acc[2 * np],     al0, al1, al2, al3, bh0, bh1);
                MMA16816(acc[2 * np + 1], al0, al1, al2, al3, bh2, bh3);
            }
        }
        __syncthreads();
    }

    // epilogue: h_prime
#pragma unroll
    for (int nt = 0; nt < 16; nt++) {
        *(float2*)(out + (size_t)row0 * OUTF + nt * 8 + 2 * tq) = make_float2(acc[nt].x, acc[nt].y);
        *(float2*)(out + (size_t)row1 * OUTF + nt * 8 + 2 * tq) = make_float2(acc[nt].z, acc[nt].w);
    }
}

extern "C" void kernel_launch(void* const* d_in, const int* in_sizes, int n_in,
                              void* d_out, int out_size) {
    const float* h   = (const float*)d_in[0];
    const int*   adj = (const int*)d_in[1];
    const float* W   = (const float*)d_in[2];
    const float* a   = (const float*)d_in[3];
    float* out = (float*)d_out;

    cudaFuncSetAttribute(k_main, cudaFuncAttributeMaxDynamicSharedMemorySize, SMEM_MAIN);

    k_ht<<<KN / 8, 256>>>(h, W);
    k_srctgt<<<KN, 128>>>(a);
    k_split<<<dim3(KN / 32, OUTF / 32), 256>>>();
    k_bits<<<KN / 8, 256>>>(adj);
    k_main<<<KN / 128, 256, SMEM_MAIN>>>(out);
}

// round 5
// speedup vs baseline: 2.9520x; 1.0577x over previous
#include <cuda_runtime.h>
#include <cuda_fp16.h>
#include <cstdint>

// GraphAttentionLayer: N=12288, IN_F=256, OUT_F=128, slope=0.2
// out = [h_prime (N x 128) | attention (N x N)] fp32.
//
//  k_ht     : h_t = h @ W
//  k_srctgt : src/tgt dots + exp tables (exp(leaky(s)) = max(Es*Et, Es2*Et2))
//  k_split  : h_t -> transposed fp16 hi/lo  (MMA B operand)
//  k_bits   : adj -> packed bitmask + folded softmax denominators (vectorized)
//  k_main   : 512 thr / 16 warps (4/SMSP), col-split halves; P fragments in
//             registers (stored as attention by half 0), B via cp.async
//             double-buffer + ldmatrix, mma.sync m16n8k16 3-term hi/lo split.

#define KN    12288
#define INF_  256
#define OUTF  128
#define NWORDS (KN / 32)     // 384
#define CH    128            // K-chunk
#define NC    (KN / CH)      // 96

__device__ float g_ht[(size_t)KN * OUTF];
__device__ __half g_htT_hi[(size_t)OUTF * KN];
__device__ __half g_htT_lo[(size_t)OUTF * KN];
__device__ __align__(16) float g_Es[KN], g_Es2[KN], g_Etgt[KN], g_Etgt2[KN];
__device__ float g_A[KN], g_B[KN];
__device__ __align__(16) uint32_t g_bits[(size_t)KN * NWORDS];

// ---------------- helpers ----------------
__device__ __forceinline__ uint32_t smem_u32(const void* p) {
    uint32_t a;
    asm("{ .reg .u64 t; cvta.to.shared.u64 t, %1; cvt.u32.u64 %0, t; }" : "=r"(a) : "l"(p));
    return a;
}
__device__ __forceinline__ uint32_t packh2(float p0, float p1) {
    uint32_t r;
    asm("cvt.rn.f16x2.f32 %0, %1, %2;" : "=r"(r) : "f"(p1), "f"(p0));
    return r;
}
__device__ __forceinline__ float h2lo(uint32_t v) {
    return __half2float(__ushort_as_half((unsigned short)(v & 0xFFFFu)));
}
__device__ __forceinline__ float h2hi(uint32_t v) {
    return __half2float(__ushort_as_half((unsigned short)(v >> 16)));
}

#define MMA16816(d, a0, a1, a2, a3, b0, b1) \
    asm volatile( \
        "mma.sync.aligned.m16n8k16.row.col.f32.f16.f16.f32 " \
        "{%0,%1,%2,%3}, {%4,%5,%6,%7}, {%8,%9}, {%0,%1,%2,%3};" \
        : "+f"((d).x), "+f"((d).y), "+f"((d).z), "+f"((d).w) \
        : "r"(a0), "r"(a1), "r"(a2), "r"(a3), "r"(b0), "r"(b1))

#define LDMX4(r0, r1, r2, r3, ad) \
    asm volatile("ldmatrix.sync.aligned.m8n8.x4.shared.b16 {%0,%1,%2,%3}, [%4];" \
                 : "=r"(r0), "=r"(r1), "=r"(r2), "=r"(r3) : "r"(ad))

#define CP16(dst, src) \
    asm volatile("cp.async.cg.shared.global [%0], [%1], 16;" :: "r"(dst), "l"(src) : "memory")
#define CP_COMMIT() asm volatile("cp.async.commit_group;" ::: "memory")
#define CP_WAIT1()  asm volatile("cp.async.wait_group 1;" ::: "memory")
#define CP_WAIT0()  asm volatile("cp.async.wait_group 0;" ::: "memory")

// ---------------- K1: h_t = h @ W ----------------
__global__ void __launch_bounds__(256) k_ht(const float* __restrict__ h,
                                            const float* __restrict__ W) {
    __shared__ float h_s[8 * INF_];
    int t = threadIdx.x;
    int r0 = blockIdx.x * 8;
    for (int idx = t; idx < 8 * INF_; idx += 256)
        h_s[idx] = h[(size_t)r0 * INF_ + idx];
    __syncthreads();
    int c  = t & 127;
    int rg = t >> 7;
    float acc[4] = {0.f, 0.f, 0.f, 0.f};
    for (int k = 0; k < INF_; k++) {
        float w = W[k * OUTF + c];
#pragma unroll
        for (int rr = 0; rr < 4; rr++)
            acc[rr] = fmaf(h_s[(rg * 4 + rr) * INF_ + k], w, acc[rr]);
    }
#pragma unroll
    for (int rr = 0; rr < 4; rr++)
        g_ht[(size_t)(r0 + rg * 4 + rr) * OUTF + c] = acc[rr];
}

// ---------------- K1b: src/tgt + exp tables ----------------
__global__ void __launch_bounds__(128) k_srctgt(const float* __restrict__ a) {
    int r = blockIdx.x;
    int t = threadIdx.x;
    float v  = g_ht[(size_t)r * OUTF + t];
    float s1 = v * a[t];
    float s2 = v * a[OUTF + t];
#pragma unroll
    for (int o = 16; o > 0; o >>= 1) {
        s1 += __shfl_down_sync(0xFFFFFFFFu, s1, o);
        s2 += __shfl_down_sync(0xFFFFFFFFu, s2, o);
    }
    __shared__ float red[8];
    int w = t >> 5, l = t & 31;
    if (l == 0) { red[w] = s1; red[4 + w] = s2; }
    __syncthreads();
    if (t == 0) {
        float src = red[0] + red[1] + red[2] + red[3];
        float tgt = red[4] + red[5] + red[6] + red[7];
        g_Es[r]    = expf(src);
        g_Es2[r]   = expf(0.2f * src);
        g_Etgt[r]  = expf(tgt);
        g_Etgt2[r] = expf(0.2f * tgt);
    }
}

// ---------------- K1c: transpose + fp16 hi/lo split ----------------
__global__ void __launch_bounds__(256) k_split() {
    __shared__ float sm[32][33];
    int t  = threadIdx.x;
    int tx = t & 31, ty = t >> 5;
    int j0 = blockIdx.x * 32;
    int c0 = blockIdx.y * 32;
#pragma unroll
    for (int q = 0; q < 4; q++)
        sm[ty + q * 8][tx] = g_ht[(size_t)(j0 + ty + q * 8) * OUTF + c0 + tx];
    __syncthreads();
#pragma unroll
    for (int q = 0; q < 4; q++) {
        int c = c0 + ty + q * 8;
        float v = sm[tx][ty + q * 8];
        __half hi = __float2half_rn(v);
        __half lo = __float2half_rn(v - __half2float(hi));
        size_t idx = (size_t)c * KN + j0 + tx;
        g_htT_hi[idx] = hi;
        g_htT_lo[idx] = lo;
    }
}

// ---------------- Kbits: bitmask + row denominators (vectorized) ----------------
__global__ void __launch_bounds__(256) k_bits(const int* __restrict__ adj) {
    int w = threadIdx.x >> 5, l = threadIdx.x & 31;
    int r = blockIdx.x * 8 + w;
    float Es = g_Es[r], Es2 = g_Es2[r];
    const int4* __restrict__ arow = (const int4*)(adj + (size_t)r * KN);
    uint32_t* __restrict__ brow = g_bits + (size_t)r * NWORDS;
    const int sh = (l & 7) * 4;
    float lsum = 0.f;
#pragma unroll 2
    for (int it = 0; it < KN / 128; it++) {     // 96 iterations, 128 j per warp
        int j = it * 128 + l * 4;
        int4 m = arow[it * 32 + l];
        float4 e1 = *(const float4*)(g_Etgt + j);
        float4 e2 = *(const float4*)(g_Etgt2 + j);
        uint32_t nib = 0;
        if (m.x) { nib |= 1u; lsum += fmaxf(Es * e1.x, Es2 * e2.x); }
        if (m.y) { nib |= 2u; lsum += fmaxf(Es * e1.y, Es2 * e2.y); }
        if (m.z) { nib |= 4u; lsum += fmaxf(Es * e1.z, Es2 * e2.z); }
        if (m.w) { nib |= 8u; lsum += fmaxf(Es * e1.w, Es2 * e2.w); }
        uint32_t word = nib << sh;
        word |= __shfl_xor_sync(0xFFFFFFFFu, word, 1);
        word |= __shfl_xor_sync(0xFFFFFFFFu, word, 2);
        word |= __shfl_xor_sync(0xFFFFFFFFu, word, 4);
        if ((l & 7) == 0) brow[it * 4 + (l >> 3)] = word;
    }
#pragma unroll
    for (int o = 16; o > 0; o >>= 1) lsum += __shfl_down_sync(0xFFFFFFFFu, lsum, o);
    if (l == 0) {
        float inv = 1.0f / lsum;
        g_A[r] = Es * inv;
        g_B[r] = Es2 * inv;
    }
}

// ---------------- K2: fused P-gen + mma.sync GEMM ----------------
// 512 threads / 16 warps. Warp w: rows (w&7)*16.., col-half w>>3 (64 cols).
// B smem: row n 0..127, stride 272B (256B data + 16B pad); hi at +0, lo at
// +VERBYTES; double buffered.
#define ROWSTRIDE 272
#define VERBYTES  (128 * ROWSTRIDE)   // 34816
#define BUFBYTES  (2 * VERBYTES)      // 69632
#define SMEM_MAIN (2 * BUFBYTES)      // 139264

__global__ void __launch_bounds__(512, 1) k_main(float* __restrict__ out) {
    extern __shared__ char sm[];
    const uint32_t smb = smem_u32(sm);
    const int t  = threadIdx.x;
    const int w  = t >> 5, l = t & 31;
    const int rw = w & 7;          // row-group
    const int nh = w >> 3;         // col half 0/1
    const int g  = l >> 2, tq = l & 3;
    const int i0 = blockIdx.x * 128;
    const int row0 = i0 + rw * 16 + g;
    const int row1 = row0 + 8;

    const float aA0 = g_A[row0], bB0 = g_B[row0];
    const float aA1 = g_A[row1], bB1 = g_B[row1];
    float* __restrict__ attn0 = out + (size_t)KN * OUTF + (size_t)row0 * KN;
    float* __restrict__ attn1 = out + (size_t)KN * OUTF + (size_t)row1 * KN;
    const uint4* __restrict__ bits0 = (const uint4*)(g_bits + (size_t)row0 * NWORDS);
    const uint4* __restrict__ bits1 = (const uint4*)(g_bits + (size_t)row1 * NWORDS);

    // cp.async: thread covers rows (t>>4)+32i (i<4), 16B-vec (t&15)
    const int cpr = t >> 4;          // 0..31
    const int cpk = t & 15;
    // ldmatrix lane addressing within a 16-row group
    const uint32_t lmrow = ((l >> 4) & 1) * 8 + (l & 7);
    const uint32_t lmoff = (nh * 64 + lmrow) * ROWSTRIDE + ((l >> 3) & 1) * 16;

    float4 acc[8];
#pragma unroll
    for (int i = 0; i < 8; i++) acc[i] = make_float4(0.f, 0.f, 0.f, 0.f);

    // prologue: chunk 0 -> buf 0
#pragma unroll
    for (int i = 0; i < 4; i++) {
        int row = cpr + i * 32;
        uint32_t d = smb + row * ROWSTRIDE + cpk * 16;
        CP16(d,            g_htT_hi + (size_t)row * KN + cpk * 8);
        CP16(d + VERBYTES, g_htT_lo + (size_t)row * KN + cpk * 8);
    }
    CP_COMMIT();

    for (int c = 0; c < NC; c++) {
        const int buf = c & 1;
        if (c + 1 < NC) {
            const int jn = (c + 1) * CH;
            const uint32_t dstb = smb + (buf ^ 1) * BUFBYTES;
#pragma unroll
            for (int i = 0; i < 4; i++) {
                int row = cpr + i * 32;
                uint32_t d = dstb + row * ROWSTRIDE + cpk * 16;
                CP16(d,            g_htT_hi + (size_t)row * KN + jn + cpk * 8);
                CP16(d + VERBYTES, g_htT_lo + (size_t)row * KN + jn + cpk * 8);
            }
            CP_COMMIT();
            CP_WAIT1();
        } else {
            CP_WAIT0();
        }
        __syncthreads();

        const uint4 w0 = bits0[c];
        const uint4 w1 = bits1[c];
        const uint32_t lmb = smb + buf * BUFBYTES + lmoff;

#pragma unroll 2
        for (int kk = 0; kk < 8; kk++) {
            const int j = c * CH + kk * 16;
            float2 e1a = *(const float2*)(g_Etgt  + j + 2 * tq);
            float2 e1b = *(const float2*)(g_Etgt  + j + 2 * tq + 8);
            float2 e2a = *(const float2*)(g_Etgt2 + j + 2 * tq);
            float2 e2b = *(const float2*)(g_Etgt2 + j + 2 * tq + 8);
            const uint32_t bwa = ((const uint32_t*)&w0)[kk >> 1] >> ((kk & 1) * 16);
            const uint32_t bwb = ((const uint32_t*)&w1)[kk >> 1] >> ((kk & 1) * 16);

            float p00 = (bwa >> (2 * tq))     & 1 ? fmaxf(aA0 * e1a.x, bB0 * e2a.x) : 0.f;
            float p01 = (bwa >> (2 * tq + 1)) & 1 ? fmaxf(aA0 * e1a.y, bB0 * e2a.y) : 0.f;
            float p02 = (bwa >> (2 * tq + 8)) & 1 ? fmaxf(aA0 * e1b.x, bB0 * e2b.x) : 0.f;
            float p03 = (bwa >> (2 * tq + 9)) & 1 ? fmaxf(aA0 * e1b.y, bB0 * e2b.y) : 0.f;
            float p10 = (bwb >> (2 * tq))     & 1 ? fmaxf(aA1 * e1a.x, bB1 * e2a.x) : 0.f;
            float p11 = (bwb >> (2 * tq + 1)) & 1 ? fmaxf(aA1 * e1a.y, bB1 * e2a.y) : 0.f;
            float p12 = (bwb >> (2 * tq + 8)) & 1 ? fmaxf(aA1 * e1b.x, bB1 * e2b.x) : 0.f;
            float p13 = (bwb >> (2 * tq + 9)) & 1 ? fmaxf(aA1 * e1b.y, bB1 * e2b.y) : 0.f;

            if (nh == 0) {
                *(float2*)(attn0 + j + 2 * tq)     = make_float2(p00, p01);
                *(float2*)(attn0 + j + 2 * tq + 8) = make_float2(p02, p03);
                *(float2*)(attn1 + j + 2 * tq)     = make_float2(p10, p11);
                *(float2*)(attn1 + j + 2 * tq + 8) = make_float2(p12, p13);
            }

            const uint32_t ah0 = packh2(p00, p01);
            const uint32_t ah1 = packh2(p10, p11);
            const uint32_t ah2 = packh2(p02, p03);
            const uint32_t ah3 = packh2(p12, p13);
            const uint32_t al0 = packh2(p00 - h2lo(ah0), p01 - h2hi(ah0));
            const uint32_t al1 = packh2(p10 - h2lo(ah1), p11 - h2hi(ah1));
            const uint32_t al2 = packh2(p02 - h2lo(ah2), p03 - h2hi(ah2));
            const uint32_t al3 = packh2(p12 - h2lo(ah3), p13 - h2hi(ah3));

            const uint32_t lmk = lmb + kk * 32;
#pragma unroll
            for (int np = 0; np < 4; np++) {
                const uint32_t ad = lmk + np * (16 * ROWSTRIDE);
                uint32_t bh0, bh1, bh2, bh3, bl0, bl1, bl2, bl3;
                LDMX4(bh0, bh1, bh2, bh3, ad);
                LDMX4(bl0, bl1, bl2, bl3, ad + VERBYTES);
                MMA16816(acc[2 * np],     ah0, ah1, ah2, ah3, bh0, bh1);
                MMA16816(acc[2 * np + 1], ah0, ah1, ah2, ah3, bh2, bh3);
                MMA16816(acc[2 * np],     ah0, ah1, ah2, ah3, bl0, bl1);
                MMA16816(acc[2 * np + 1], ah0, ah1, ah2, ah3, bl2, bl3);
                MMA16816(acc[2 * np],     al0, al1, al2, al3, bh0, bh1);
                MMA16816(acc[2 * np + 1], al0, al1, al2, al3, bh2, bh3);
            }
        }
        __syncthreads();
    }

    // epilogue: h_prime (warp writes its 64-col half)
#pragma unroll
    for (int nt = 0; nt < 8; nt++) {
        int cc = nh * 64 + nt * 8 + 2 * tq;
        *(float2*)(out + (size_t)row0 * OUTF + cc) = make_float2(acc[nt].x, acc[nt].y);
        *(float2*)(out + (size_t)row1 * OUTF + cc) = make_float2(acc[nt].z, acc[nt].w);
    }
}

extern "C" void kernel_launch(void* const* d_in, const int* in_sizes, int n_in,
                              void* d_out, int out_size) {
    const float* h   = (const float*)d_in[0];
    const int*   adj = (const int*)d_in[1];
    const float* W   = (const float*)d_in[2];
    const float* a   = (const float*)d_in[3];
    float* out = (float*)d_out;

    cudaFuncSetAttribute(k_main, cudaFuncAttributeMaxDynamicSharedMemorySize, SMEM_MAIN);

    k_ht<<<KN / 8, 256>>>(h, W);
    k_srctgt<<<KN, 128>>>(a);
    k_split<<<dim3(KN / 32, OUTF / 32), 256>>>();
    k_bits<<<KN / 8, 256>>>(adj);
    k_main<<<KN / 128, 512, SMEM_MAIN>>>(out);
}

// round 6
// speedup vs baseline: 4.2891x; 1.4529x over previous
#include <cuda_runtime.h>
#include <cuda_fp16.h>
#include <cstdint>

// GraphAttentionLayer: N=12288, IN_F=256, OUT_F=128, slope=0.2
// out = [h_prime (N x 128) | attention (N x N)] fp32.
//
//  k_ht     : h_t = h @ W
//  k_srctgt : src/tgt dots + exp tables (exp(leaky(s)) = max(Es*Et, Es2*Et2))
//  k_split  : h_t -> transposed fp16 (MMA B operand, unsplit)
//  k_bits   : adj -> packed bitmask + folded denominators (smem-staged exp)
//  k_main   : grid 288 = 96 row-tiles x 3 j-thirds; P fragments in registers
//             (A split hi/lo, 2-term MMA), B via cp.async double-buffer +
//             ldmatrix; h_prime partials to scratch.
//  k_red    : sum 3 partials -> h_prime.

#define KN    12288
#define INF_  256
#define OUTF  128
#define NWORDS (KN / 32)     // 384
#define CH    128            // K-chunk
#define NSPLIT 3
#define NCL   (KN / CH / NSPLIT)   // 32 chunks per split
#define JSPAN (KN / NSPLIT)        // 4096

__device__ float g_ht[(size_t)KN * OUTF];
__device__ __half g_htT[(size_t)OUTF * KN];
__device__ __align__(16) float g_Es[KN], g_Es2[KN], g_Etgt[KN], g_Etgt2[KN];
__device__ float g_A[KN], g_B[KN];
__device__ __align__(16) uint32_t g_bits[(size_t)KN * NWORDS];
__device__ float g_part[(size_t)NSPLIT * KN * OUTF];

// ---------------- helpers ----------------
__device__ __forceinline__ uint32_t smem_u32(const void* p) {
    uint32_t a;
    asm("{ .reg .u64 t; cvta.to.shared.u64 t, %1; cvt.u32.u64 %0, t; }" : "=r"(a) : "l"(p));
    return a;
}
__device__ __forceinline__ uint32_t packh2(float p0, float p1) {
    uint32_t r;
    asm("cvt.rn.f16x2.f32 %0, %1, %2;" : "=r"(r) : "f"(p1), "f"(p0));
    return r;
}
__device__ __forceinline__ float h2lo(uint32_t v) {
    return __half2float(__ushort_as_half((unsigned short)(v & 0xFFFFu)));
}
__device__ __forceinline__ float h2hi(uint32_t v) {
    return __half2float(__ushort_as_half((unsigned short)(v >> 16)));
}

#define MMA16816(d, a0, a1, a2, a3, b0, b1) \
    asm volatile( \
        "mma.sync.aligned.m16n8k16.row.col.f32.f16.f16.f32 " \
        "{%0,%1,%2,%3}, {%4,%5,%6,%7}, {%8,%9}, {%0,%1,%2,%3};" \
        : "+f"((d).x), "+f"((d).y), "+f"((d).z), "+f"((d).w) \
        : "r"(a0), "r"(a1), "r"(a2), "r"(a3), "r"(b0), "r"(b1))

#define LDMX4(r0, r1, r2, r3, ad) \
    asm volatile("ldmatrix.sync.aligned.m8n8.x4.shared.b16 {%0,%1,%2,%3}, [%4];" \
                 : "=r"(r0), "=r"(r1), "=r"(r2), "=r"(r3) : "r"(ad))

#define CP16(dst, src) \
    asm volatile("cp.async.cg.shared.global [%0], [%1], 16;" :: "r"(dst), "l"(src) : "memory")
#define CP_COMMIT() asm volatile("cp.async.commit_group;" ::: "memory")
#define CP_WAIT1()  asm volatile("cp.async.wait_group 1;" ::: "memory")
#define CP_WAIT0()  asm volatile("cp.async.wait_group 0;" ::: "memory")

// ---------------- K1: h_t = h @ W ----------------
__global__ void __launch_bounds__(256) k_ht(const float* __restrict__ h,
                                            const float* __restrict__ W) {
    __shared__ float h_s[8 * INF_];
    int t = threadIdx.x;
    int r0 = blockIdx.x * 8;
    for (int idx = t; idx < 8 * INF_; idx += 256)
        h_s[idx] = h[(size_t)r0 * INF_ + idx];
    __syncthreads();
    int c  = t & 127;
    int rg = t >> 7;
    float acc[4] = {0.f, 0.f, 0.f, 0.f};
    for (int k = 0; k < INF_; k++) {
        float w = W[k * OUTF + c];
#pragma unroll
        for (int rr = 0; rr < 4; rr++)
            acc[rr] = fmaf(h_s[(rg * 4 + rr) * INF_ + k], w, acc[rr]);
    }
#pragma unroll
    for (int rr = 0; rr < 4; rr++)
        g_ht[(size_t)(r0 + rg * 4 + rr) * OUTF + c] = acc[rr];
}

// ---------------- K1b: src/tgt + exp tables ----------------
__global__ void __launch_bounds__(128) k_srctgt(const float* __restrict__ a) {
    int r = blockIdx.x;
    int t = threadIdx.x;
    float v  = g_ht[(size_t)r * OUTF + t];
    float s1 = v * a[t];
    float s2 = v * a[OUTF + t];
#pragma unroll
    for (int o = 16; o > 0; o >>= 1) {
        s1 += __shfl_down_sync(0xFFFFFFFFu, s1, o);
        s2 += __shfl_down_sync(0xFFFFFFFFu, s2, o);
    }
    __shared__ float red[8];
    int w = t >> 5, l = t & 31;
    if (l == 0) { red[w] = s1; red[4 + w] = s2; }
    __syncthreads();
    if (t == 0) {
        float src = red[0] + red[1] + red[2] + red[3];
        float tgt = red[4] + red[5] + red[6] + red[7];
        g_Es[r]    = expf(src);
        g_Es2[r]   = expf(0.2f * src);
        g_Etgt[r]  = expf(tgt);
        g_Etgt2[r] = expf(0.2f * tgt);
    }
}

// ---------------- K1c: transpose -> fp16 ----------------
__global__ void __launch_bounds__(256) k_split() {
    __shared__ float sm[32][33];
    int t  = threadIdx.x;
    int tx = t & 31, ty = t >> 5;
    int j0 = blockIdx.x * 32;
    int c0 = blockIdx.y * 32;
#pragma unroll
    for (int q = 0; q < 4; q++)
        sm[ty + q * 8][tx] = g_ht[(size_t)(j0 + ty + q * 8) * OUTF + c0 + tx];
    __syncthreads();
#pragma unroll
    for (int q = 0; q < 4; q++) {
        int c = c0 + ty + q * 8;
        g_htT[(size_t)c * KN + j0 + tx] = __float2half_rn(sm[tx][ty + q * 8]);
    }
}

// ---------------- Kbits: bitmask + denominators (smem-staged exp) ----------------
__global__ void __launch_bounds__(256) k_bits(const int* __restrict__ adj) {
    __shared__ __align__(16) float sE1[1024], sE2[1024];
    int t = threadIdx.x;
    int w = t >> 5, l = t & 31;
    int r = blockIdx.x * 8 + w;
    float Es = g_Es[r], Es2 = g_Es2[r];
    const int4* __restrict__ arow = (const int4*)(adj + (size_t)r * KN);
    uint32_t* __restrict__ brow = g_bits + (size_t)r * NWORDS;
    const int sh = (l & 7) * 4;
    float lsum = 0.f;

    for (int jc = 0; jc < KN / 1024; jc++) {    // 12 chunks
        __syncthreads();
        *(float4*)&sE1[t * 4] = *(const float4*)(g_Etgt  + jc * 1024 + t * 4);
        *(float4*)&sE2[t * 4] = *(const float4*)(g_Etgt2 + jc * 1024 + t * 4);
        __syncthreads();
#pragma unroll
        for (int it = 0; it < 8; it++) {        // 128 j per warp per it
            int4 m = arow[jc * 256 + it * 32 + l];
            float4 e1 = *(const float4*)&sE1[it * 128 + l * 4];
            float4 e2 = *(const float4*)&sE2[it * 128 + l * 4];
            uint32_t nib = 0;
            if (m.x) { nib |= 1u; lsum += fmaxf(Es * e1.x, Es2 * e2.x); }
            if (m.y) { nib |= 2u; lsum += fmaxf(Es * e1.y, Es2 * e2.y); }
            if (m.z) { nib |= 4u; lsum += fmaxf(Es * e1.z, Es2 * e2.z); }
            if (m.w) { nib |= 8u; lsum += fmaxf(Es * e1.w, Es2 * e2.w); }
            uint32_t word = nib << sh;
            word |= __shfl_xor_sync(0xFFFFFFFFu, word, 1);
            word |= __shfl_xor_sync(0xFFFFFFFFu, word, 2);
            word |= __shfl_xor_sync(0xFFFFFFFFu, word, 4);
            if ((l & 7) == 0) brow[jc * 32 + it * 4 + (l >> 3)] = word;
        }
    }
#pragma unroll
    for (int o = 16; o > 0; o >>= 1) lsum += __shfl_down_sync(0xFFFFFFFFu, lsum, o);
    if (l == 0) {
        float inv = 1.0f / lsum;
        g_A[r] = Es * inv;
        g_B[r] = Es2 * inv;
    }
}

// ---------------- K2: fused P-gen + mma.sync GEMM (2-term, K-split 3) --------
#define ROWSTRIDE 272
#define VERBYTES  (128 * ROWSTRIDE)   // 34816 (fp16 B, single version)
#define SMEM_MAIN (2 * VERBYTES)      // 69632 double buffered

__global__ void __launch_bounds__(512, 1) k_main(float* __restrict__ out) {
    extern __shared__ char sm[];
    const uint32_t smb = smem_u32(sm);
    const int t  = threadIdx.x;
    const int w  = t >> 5, l = t & 31;
    const int rw = w & 7;          // row-group
    const int nh = w >> 3;         // col half 0/1
    const int g  = l >> 2, tq = l & 3;
    const int ti = blockIdx.x / NSPLIT;     // row tile
    const int js = blockIdx.x % NSPLIT;     // j third
    const int i0 = ti * 128;
    const int jbase = js * JSPAN;
    const int row0 = i0 + rw * 16 + g;
    const int row1 = row0 + 8;

    const float aA0 = g_A[row0], bB0 = g_B[row0];
    const float aA1 = g_A[row1], bB1 = g_B[row1];
    float* __restrict__ attn0 = out + (size_t)KN * OUTF + (size_t)row0 * KN;
    float* __restrict__ attn1 = out + (size_t)KN * OUTF + (size_t)row1 * KN;
    const uint4* __restrict__ bits0 = (const uint4*)(g_bits + (size_t)row0 * NWORDS) + js * NCL;
    const uint4* __restrict__ bits1 = (const uint4*)(g_bits + (size_t)row1 * NWORDS) + js * NCL;

    const int cpr = t >> 4;          // 0..31
    const int cpk = t & 15;
    const uint32_t lmrow = ((l >> 4) & 1) * 8 + (l & 7);
    const uint32_t lmoff = (nh * 64 + lmrow) * ROWSTRIDE + ((l >> 3) & 1) * 16;

    float4 acc[8];
#pragma unroll
    for (int i = 0; i < 8; i++) acc[i] = make_float4(0.f, 0.f, 0.f, 0.f);

    // prologue: chunk 0 -> buf 0
#pragma unroll
    for (int i = 0; i < 4; i++) {
        int row = cpr + i * 32;
        CP16(smb + row * ROWSTRIDE + cpk * 16,
             g_htT + (size_t)row * KN + jbase + cpk * 8);
    }
    CP_COMMIT();

    for (int c = 0; c < NCL; c++) {
        const int buf = c & 1;
        if (c + 1 < NCL) {
            const int jn = jbase + (c + 1) * CH;
            const uint32_t dstb = smb + (buf ^ 1) * VERBYTES;
#pragma unroll
            for (int i = 0; i < 4; i++) {
                int row = cpr + i * 32;
                CP16(dstb + row * ROWSTRIDE + cpk * 16,
                     g_htT + (size_t)row * KN + jn + cpk * 8);
            }
            CP_COMMIT();
            CP_WAIT1();
        } else {
            CP_WAIT0();
        }
        __syncthreads();

        const uint4 w0 = bits0[c];
        const uint4 w1 = bits1[c];
        const uint32_t lmb = smb + buf * VERBYTES + lmoff;

#pragma unroll 2
        for (int kk = 0; kk < 8; kk++) {
            const int j = jbase + c * CH + kk * 16;
            float2 e1a = *(const float2*)(g_Etgt  + j + 2 * tq);
            float2 e1b = *(const float2*)(g_Etgt  + j + 2 * tq + 8);
            float2 e2a = *(const float2*)(g_Etgt2 + j + 2 * tq);
            float2 e2b = *(const float2*)(g_Etgt2 + j + 2 * tq + 8);
            const uint32_t bwa = ((const uint32_t*)&w0)[kk >> 1] >> ((kk & 1) * 16);
            const uint32_t bwb = ((const uint32_t*)&w1)[kk >> 1] >> ((kk & 1) * 16);

            float p00 = (bwa >> (2 * tq))     & 1 ? fmaxf(aA0 * e1a.x, bB0 * e2a.x) : 0.f;
            float p01 = (bwa >> (2 * tq + 1)) & 1 ? fmaxf(aA0 * e1a.y, bB0 * e2a.y) : 0.f;
            float p02 = (bwa >> (2 * tq + 8)) & 1 ? fmaxf(aA0 * e1b.x, bB0 * e2b.x) : 0.f;
            float p03 = (bwa >> (2 * tq + 9)) & 1 ? fmaxf(aA0 * e1b.y, bB0 * e2b.y) : 0.f;
            float p10 = (bwb >> (2 * tq))     & 1 ? fmaxf(aA1 * e1a.x, bB1 * e2a.x) : 0.f;
            float p11 = (bwb >> (2 * tq + 1)) & 1 ? fmaxf(aA1 * e1a.y, bB1 * e2a.y) : 0.f;
            float p12 = (bwb >> (2 * tq + 8)) & 1 ? fmaxf(aA1 * e1b.x, bB1 * e2b.x) : 0.f;
            float p13 = (bwb >> (2 * tq + 9)) & 1 ? fmaxf(aA1 * e1b.y, bB1 * e2b.y) : 0.f;

            if (nh == 0) {
                *(float2*)(attn0 + j + 2 * tq)     = make_float2(p00, p01);
                *(float2*)(attn0 + j + 2 * tq + 8) = make_float2(p02, p03);
                *(float2*)(attn1 + j + 2 * tq)     = make_float2(p10, p11);
                *(float2*)(attn1 + j + 2 * tq + 8) = make_float2(p12, p13);
            }

            const uint32_t ah0 = packh2(p00, p01);
            const uint32_t ah1 = packh2(p10, p11);
            const uint32_t ah2 = packh2(p02, p03);
            const uint32_t ah3 = packh2(p12, p13);
            const uint32_t al0 = packh2(p00 - h2lo(ah0), p01 - h2hi(ah0));
            const uint32_t al1 = packh2(p10 - h2lo(ah1), p11 - h2hi(ah1));
            const uint32_t al2 = packh2(p02 - h2lo(ah2), p03 - h2hi(ah2));
            const uint32_t al3 = packh2(p12 - h2lo(ah3), p13 - h2hi(ah3));

            const uint32_t lmk = lmb + kk * 32;
#pragma unroll
            for (int np = 0; np < 4; np++) {
                uint32_t bh0, bh1, bh2, bh3;
                LDMX4(bh0, bh1, bh2, bh3, lmk + np * (16 * ROWSTRIDE));
                MMA16816(acc[2 * np],     ah0, ah1, ah2, ah3, bh0, bh1);
                MMA16816(acc[2 * np + 1], ah0, ah1, ah2, ah3, bh2, bh3);
                MMA16816(acc[2 * np],     al0, al1, al2, al3, bh0, bh1);
                MMA16816(acc[2 * np + 1], al0, al1, al2, al3, bh2, bh3);
            }
        }
        __syncthreads();
    }

    // epilogue: h_prime partial for this j-third
    float* __restrict__ part = g_part + (size_t)js * KN * OUTF;
#pragma unroll
    for (int nt = 0; nt < 8; nt++) {
        int cc = nh * 64 + nt * 8 + 2 * tq;
        *(float2*)(part + (size_t)row0 * OUTF + cc) = make_float2(acc[nt].x, acc[nt].y);
        *(float2*)(part + (size_t)row1 * OUTF + cc) = make_float2(acc[nt].z, acc[nt].w);
    }
}

// ---------------- K3: reduce partials ----------------
__global__ void __launch_bounds__(256) k_red(float* __restrict__ out) {
    const size_t SZ = (size_t)KN * OUTF;
    size_t idx = ((size_t)blockIdx.x * 256 + threadIdx.x) * 4;
    float4 a = *(const float4*)(g_part + idx);
    float4 b = *(const float4*)(g_part + SZ + idx);
    float4 c = *(const float4*)(g_part + 2 * SZ + idx);
    *(float4*)(out + idx) = make_float4(a.x + b.x + c.x, a.y + b.y + c.y,
                                        a.z + b.z + c.z, a.w + b.w + c.w);
}

extern "C" void kernel_launch(void* const* d_in, const int* in_sizes, int n_in,
                              void* d_out, int out_size) {
    const float* h   = (const float*)d_in[0];
    const int*   adj = (const int*)d_in[1];
    const float* W   = (const float*)d_in[2];
    const float* a   = (const float*)d_in[3];
    float* out = (float*)d_out;

    cudaFuncSetAttribute(k_main, cudaFuncAttributeMaxDynamicSharedMemorySize, SMEM_MAIN);

    k_ht<<<KN / 8, 256>>>(h, W);
    k_srctgt<<<KN, 128>>>(a);
    k_split<<<dim3(KN / 32, OUTF / 32), 256>>>();
    k_bits<<<KN / 8, 256>>>(adj);
    k_main<<<(KN / 128) * NSPLIT, 512, SMEM_MAIN>>>(out);
    k_red<<<(KN * OUTF) / (256 * 4), 256>>>(out);
}

// round 7
// speedup vs baseline: 5.4043x; 1.2600x over previous
#include <cuda_runtime.h>
#include <cuda_fp16.h>
#include <cstdint>

// GraphAttentionLayer: N=12288, IN_F=256, OUT_F=128, slope=0.2
// out = [h_prime (N x 128) | attention (N x N)] fp32.
//
//  k_ht     : h_t = h @ W
//  k_srctgt : src/tgt dots + exp tables (exp(leaky(s)) = max(Es*Et, Es2*Et2))
//  k_split  : h_t -> transposed fp16 (MMA B operand)
//  k_bits   : adj -> packed bitmask + folded denominators (smem-staged exp)
//  k_main   : grid 288 = 96 row-tiles x 3 j-thirds; P fragments in registers
//             (fp16, 1-term MMA), B via cp.async double-buffer + ldmatrix;
//             streaming stores for attention; h_prime partials to scratch.
//  k_red    : sum 3 partials -> h_prime.

#define KN    12288
#define INF_  256
#define OUTF  128
#define NWORDS (KN / 32)     // 384
#define CH    128            // K-chunk
#define NSPLIT 3
#define NCL   (KN / CH / NSPLIT)   // 32 chunks per split
#define JSPAN (KN / NSPLIT)        // 4096

__device__ float g_ht[(size_t)KN * OUTF];
__device__ __half g_htT[(size_t)OUTF * KN];
__device__ __align__(16) float g_Es[KN], g_Es2[KN], g_Etgt[KN], g_Etgt2[KN];
__device__ float g_A[KN], g_B[KN];
__device__ __align__(16) uint32_t g_bits[(size_t)KN * NWORDS];
__device__ float g_part[(size_t)NSPLIT * KN * OUTF];

// ---------------- helpers ----------------
__device__ __forceinline__ uint32_t smem_u32(const void* p) {
    uint32_t a;
    asm("{ .reg .u64 t; cvta.to.shared.u64 t, %1; cvt.u32.u64 %0, t; }" : "=r"(a) : "l"(p));
    return a;
}
__device__ __forceinline__ uint32_t packh2(float p0, float p1) {
    uint32_t r;
    asm("cvt.rn.f16x2.f32 %0, %1, %2;" : "=r"(r) : "f"(p1), "f"(p0));
    return r;
}
// streaming stores (write-once, bypass-ish L2 allocation priority)
__device__ __forceinline__ void stcs2(float* p, float a, float b) {
    asm volatile("st.global.cs.v2.f32 [%0], {%1, %2};" :: "l"(p), "f"(a), "f"(b) : "memory");
}
__device__ __forceinline__ int4 ldcs4(const int4* p) {
    int4 v;
    asm volatile("ld.global.cs.nc.v4.s32 {%0,%1,%2,%3}, [%4];"
                 : "=r"(v.x), "=r"(v.y), "=r"(v.z), "=r"(v.w) : "l"(p));
    return v;
}

#define MMA16816(d, a0, a1, a2, a3, b0, b1) \
    asm volatile( \
        "mma.sync.aligned.m16n8k16.row.col.f32.f16.f16.f32 " \
        "{%0,%1,%2,%3}, {%4,%5,%6,%7}, {%8,%9}, {%0,%1,%2,%3};" \
        : "+f"((d).x), "+f"((d).y), "+f"((d).z), "+f"((d).w) \
        : "r"(a0), "r"(a1), "r"(a2), "r"(a3), "r"(b0), "r"(b1))

#define LDMX4(r0, r1, r2, r3, ad) \
    asm volatile("ldmatrix.sync.aligned.m8n8.x4.shared.b16 {%0,%1,%2,%3}, [%4];" \
                 : "=r"(r0), "=r"(r1), "=r"(r2), "=r"(r3) : "r"(ad))

#define CP16(dst, src) \
    asm volatile("cp.async.cg.shared.global [%0], [%1], 16;" :: "r"(dst), "l"(src) : "memory")
#define CP_COMMIT() asm volatile("cp.async.commit_group;" ::: "memory")
#define CP_WAIT1()  asm volatile("cp.async.wait_group 1;" ::: "memory")
#define CP_WAIT0()  asm volatile("cp.async.wait_group 0;" ::: "memory")

// ---------------- K1: h_t = h @ W ----------------
__global__ void __launch_bounds__(256) k_ht(const float* __restrict__ h,
                                            const float* __restrict__ W) {
    __shared__ float h_s[8 * INF_];
    int t = threadIdx.x;
    int r0 = blockIdx.x * 8;
    for (int idx = t; idx < 8 * INF_; idx += 256)
        h_s[idx] = h[(size_t)r0 * INF_ + idx];
    __syncthreads();
    int c  = t & 127;
    int rg = t >> 7;
    float acc[4] = {0.f, 0.f, 0.f, 0.f};
    for (int k = 0; k < INF_; k++) {
        float w = W[k * OUTF + c];
#pragma unroll
        for (int rr = 0; rr < 4; rr++)
            acc[rr] = fmaf(h_s[(rg * 4 + rr) * INF_ + k], w, acc[rr]);
    }
#pragma unroll
    for (int rr = 0; rr < 4; rr++)
        g_ht[(size_t)(r0 + rg * 4 + rr) * OUTF + c] = acc[rr];
}

// ---------------- K1b: src/tgt + exp tables ----------------
__global__ void __launch_bounds__(128) k_srctgt(const float* __restrict__ a) {
    int r = blockIdx.x;
    int t = threadIdx.x;
    float v  = g_ht[(size_t)r * OUTF + t];
    float s1 = v * a[t];
    float s2 = v * a[OUTF + t];
#pragma unroll
    for (int o = 16; o > 0; o >>= 1) {
        s1 += __shfl_down_sync(0xFFFFFFFFu, s1, o);
        s2 += __shfl_down_sync(0xFFFFFFFFu, s2, o);
    }
    __shared__ float red[8];
    int w = t >> 5, l = t & 31;
    if (l == 0) { red[w] = s1; red[4 + w] = s2; }
    __syncthreads();
    if (t == 0) {
        float src = red[0] + red[1] + red[2] + red[3];
        float tgt = red[4] + red[5] + red[6] + red[7];
        g_Es[r]    = expf(src);
        g_Es2[r]   = expf(0.2f * src);
        g_Etgt[r]  = expf(tgt);
        g_Etgt2[r] = expf(0.2f * tgt);
    }
}

// ---------------- K1c: transpose -> fp16 ----------------
__global__ void __launch_bounds__(256) k_split() {
    __shared__ float sm[32][33];
    int t  = threadIdx.x;
    int tx = t & 31, ty = t >> 5;
    int j0 = blockIdx.x * 32;
    int c0 = blockIdx.y * 32;
#pragma unroll
    for (int q = 0; q < 4; q++)
        sm[ty + q * 8][tx] = g_ht[(size_t)(j0 + ty + q * 8) * OUTF + c0 + tx];
    __syncthreads();
#pragma unroll
    for (int q = 0; q < 4; q++) {
        int c = c0 + ty + q * 8;
        g_htT[(size_t)c * KN + j0 + tx] = __float2half_rn(sm[tx][ty + q * 8]);
    }
}

// ---------------- Kbits: bitmask + denominators (smem-staged exp) ----------------
__global__ void __launch_bounds__(256) k_bits(const int* __restrict__ adj) {
    __shared__ __align__(16) float sE1[1024], sE2[1024];
    int t = threadIdx.x;
    int w = t >> 5, l = t & 31;
    int r = blockIdx.x * 8 + w;
    float Es = g_Es[r], Es2 = g_Es2[r];
    const int4* __restrict__ arow = (const int4*)(adj + (size_t)r * KN);
    uint32_t* __restrict__ brow = g_bits + (size_t)r * NWORDS;
    const int sh = (l & 7) * 4;
    float lsum = 0.f;

    for (int jc = 0; jc < KN / 1024; jc++) {    // 12 chunks
        __syncthreads();
        *(float4*)&sE1[t * 4] = *(const float4*)(g_Etgt  + jc * 1024 + t * 4);
        *(float4*)&sE2[t * 4] = *(const float4*)(g_Etgt2 + jc * 1024 + t * 4);
        __syncthreads();
#pragma unroll
        for (int it = 0; it < 8; it++) {        // 128 j per warp per it
            int4 m = ldcs4(arow + jc * 256 + it * 32 + l);
            float4 e1 = *(const float4*)&sE1[it * 128 + l * 4];
            float4 e2 = *(const float4*)&sE2[it * 128 + l * 4];
            uint32_t nib = 0;
            if (m.x) { nib |= 1u; lsum += fmaxf(Es * e1.x, Es2 * e2.x); }
            if (m.y) { nib |= 2u; lsum += fmaxf(Es * e1.y, Es2 * e2.y); }
            if (m.z) { nib |= 4u; lsum += fmaxf(Es * e1.z, Es2 * e2.z); }
            if (m.w) { nib |= 8u; lsum += fmaxf(Es * e1.w, Es2 * e2.w); }
            uint32_t word = nib << sh;
            word |= __shfl_xor_sync(0xFFFFFFFFu, word, 1);
            word |= __shfl_xor_sync(0xFFFFFFFFu, word, 2);
            word |= __shfl_xor_sync(0xFFFFFFFFu, word, 4);
            if ((l & 7) == 0) brow[jc * 32 + it * 4 + (l >> 3)] = word;
        }
    }
#pragma unroll
    for (int o = 16; o > 0; o >>= 1) lsum += __shfl_down_sync(0xFFFFFFFFu, lsum, o);
    if (l == 0) {
        float inv = 1.0f / lsum;
        g_A[r] = Es * inv;
        g_B[r] = Es2 * inv;
    }
}

// ---------------- K2: fused P-gen + mma.sync GEMM (1-term, K-split 3) --------
#define ROWSTRIDE 272
#define VERBYTES  (128 * ROWSTRIDE)   // 34816
#define SMEM_MAIN (2 * VERBYTES)      // 69632 double buffered

__global__ void __launch_bounds__(512, 1) k_main(float* __restrict__ out) {
    extern __shared__ char sm[];
    const uint32_t smb = smem_u32(sm);
    const int t  = threadIdx.x;
    const int w  = t >> 5, l = t & 31;
    const int rw = w & 7;          // row-group
    const int nh = w >> 3;         // col half 0/1
    const int g  = l >> 2, tq = l & 3;
    const int ti = blockIdx.x / NSPLIT;     // row tile
    const int js = blockIdx.x % NSPLIT;     // j third
    const int i0 = ti * 128;
    const int jbase = js * JSPAN;
    const int row0 = i0 + rw * 16 + g;
    const int row1 = row0 + 8;

    const float aA0 = g_A[row0], bB0 = g_B[row0];
    const float aA1 = g_A[row1], bB1 = g_B[row1];
    float* __restrict__ attn0 = out + (size_t)KN * OUTF + (size_t)row0 * KN;
    float* __restrict__ attn1 = out + (size_t)KN * OUTF + (size_t)row1 * KN;
    const uint4* __restrict__ bits0 = (const uint4*)(g_bits + (size_t)row0 * NWORDS) + js * NCL;
    const uint4* __restrict__ bits1 = (const uint4*)(g_bits + (size_t)row1 * NWORDS) + js * NCL;

    const int cpr = t >> 4;          // 0..31
    const int cpk = t & 15;
    const uint32_t lmrow = ((l >> 4) & 1) * 8 + (l & 7);
    const uint32_t lmoff = (nh * 64 + lmrow) * ROWSTRIDE + ((l >> 3) & 1) * 16;

    float4 acc[8];
#pragma unroll
    for (int i = 0; i < 8; i++) acc[i] = make_float4(0.f, 0.f, 0.f, 0.f);

    // prologue: chunk 0 -> buf 0
#pragma unroll
    for (int i = 0; i < 4; i++) {
        int row = cpr + i * 32;
        CP16(smb + row * ROWSTRIDE + cpk * 16,
             g_htT + (size_t)row * KN + jbase + cpk * 8);
    }
    CP_COMMIT();

    for (int c = 0; c < NCL; c++) {
        const int buf = c & 1;
        if (c + 1 < NCL) {
            const int jn = jbase + (c + 1) * CH;
            const uint32_t dstb = smb + (buf ^ 1) * VERBYTES;
#pragma unroll
            for (int i = 0; i < 4; i++) {
                int row = cpr + i * 32;
                CP16(dstb + row * ROWSTRIDE + cpk * 16,
                     g_htT + (size_t)row * KN + jn + cpk * 8);
            }
            CP_COMMIT();
            CP_WAIT1();
        } else {
            CP_WAIT0();
        }
        __syncthreads();

        const uint4 w0 = bits0[c];
        const uint4 w1 = bits1[c];
        const uint32_t lmb = smb + buf * VERBYTES + lmoff;

#pragma unroll 2
        for (int kk = 0; kk < 8; kk++) {
            const int j = jbase + c * CH + kk * 16;
            float2 e1a = *(const float2*)(g_Etgt  + j + 2 * tq);
            float2 e1b = *(const float2*)(g_Etgt  + j + 2 * tq + 8);
            float2 e2a = *(const float2*)(g_Etgt2 + j + 2 * tq);
            float2 e2b = *(const float2*)(g_Etgt2 + j + 2 * tq + 8);
            const uint32_t bwa = ((const uint32_t*)&w0)[kk >> 1] >> ((kk & 1) * 16);
            const uint32_t bwb = ((const uint32_t*)&w1)[kk >> 1] >> ((kk & 1) * 16);

            float p00 = (bwa >> (2 * tq))     & 1 ? fmaxf(aA0 * e1a.x, bB0 * e2a.x) : 0.f;
            float p01 = (bwa >> (2 * tq + 1)) & 1 ? fmaxf(aA0 * e1a.y, bB0 * e2a.y) : 0.f;
            float p02 = (bwa >> (2 * tq + 8)) & 1 ? fmaxf(aA0 * e1b.x, bB0 * e2b.x) : 0.f;
            float p03 = (bwa >> (2 * tq + 9)) & 1 ? fmaxf(aA0 * e1b.y, bB0 * e2b.y) : 0.f;
            float p10 = (bwb >> (2 * tq))     & 1 ? fmaxf(aA1 * e1a.x, bB1 * e2a.x) : 0.f;
            float p11 = (bwb >> (2 * tq + 1)) & 1 ? fmaxf(aA1 * e1a.y, bB1 * e2a.y) : 0.f;
            float p12 = (bwb >> (2 * tq + 8)) & 1 ? fmaxf(aA1 * e1b.x, bB1 * e2b.x) : 0.f;
            float p13 = (bwb >> (2 * tq + 9)) & 1 ? fmaxf(aA1 * e1b.y, bB1 * e2b.y) : 0.f;

            if (nh == 0) {
                stcs2(attn0 + j + 2 * tq,     p00, p01);
                stcs2(attn0 + j + 2 * tq + 8, p02, p03);
                stcs2(attn1 + j + 2 * tq,     p10, p11);
                stcs2(attn1 + j + 2 * tq + 8, p12, p13);
            }

            const uint32_t ah0 = packh2(p00, p01);
            const uint32_t ah1 = packh2(p10, p11);
            const uint32_t ah2 = packh2(p02, p03);
            const uint32_t ah3 = packh2(p12, p13);

            const uint32_t lmk = lmb + kk * 32;
#pragma unroll
            for (int np = 0; np < 4; np++) {
                uint32_t bh0, bh1, bh2, bh3;
                LDMX4(bh0, bh1, bh2, bh3, lmk + np * (16 * ROWSTRIDE));
                MMA16816(acc[2 * np],     ah0, ah1, ah2, ah3, bh0, bh1);
                MMA16816(acc[2 * np + 1], ah0, ah1, ah2, ah3, bh2, bh3);
            }
        }
        __syncthreads();
    }

    // epilogue: h_prime partial for this j-third
    float* __restrict__ part = g_part + (size_t)js * KN * OUTF;
#pragma unroll
    for (int nt = 0; nt < 8; nt++) {
        int cc = nh * 64 + nt * 8 + 2 * tq;
        *(float2*)(part + (size_t)row0 * OUTF + cc) = make_float2(acc[nt].x, acc[nt].y);
        *(float2*)(part + (size_t)row1 * OUTF + cc) = make_float2(acc[nt].z, acc[nt].w);
    }
}

// ---------------- K3: reduce partials ----------------
__global__ void __launch_bounds__(256) k_red(float* __restrict__ out) {
    const size_t SZ = (size_t)KN * OUTF;
    size_t idx = ((size_t)blockIdx.x * 256 + threadIdx.x) * 4;
    float4 a = *(const float4*)(g_part + idx);
    float4 b = *(const float4*)(g_part + SZ + idx);
    float4 c = *(const float4*)(g_part + 2 * SZ + idx);
    *(float4*)(out + idx) = make_float4(a.x + b.x + c.x, a.y + b.y + c.y,
                                        a.z + b.z + c.z, a.w + b.w + c.w);
}

extern "C" void kernel_launch(void* const* d_in, const int* in_sizes, int n_in,
                              void* d_out, int out_size) {
    const float* h   = (const float*)d_in[0];
    const int*   adj = (const int*)d_in[1];
    const float* W   = (const float*)d_in[2];
    const float* a   = (const float*)d_in[3];
    float* out = (float*)d_out;

    cudaFuncSetAttribute(k_main, cudaFuncAttributeMaxDynamicSharedMemorySize, SMEM_MAIN);

    k_ht<<<KN / 8, 256>>>(h, W);
    k_srctgt<<<KN, 128>>>(a);
    k_split<<<dim3(KN / 32, OUTF / 32), 256>>>();
    k_bits<<<KN / 8, 256>>>(adj);
    k_main<<<(KN / 128) * NSPLIT, 512, SMEM_MAIN>>>(out);
    k_red<<<(KN * OUTF) / (256 * 4), 256>>>(out);
}

// round 8
// speedup vs baseline: 5.8353x; 1.0797x over previous
#include <cuda_runtime.h>
#include <cuda_fp16.h>
#include <cstdint>

// GraphAttentionLayer: N=12288, IN_F=256, OUT_F=128, slope=0.2
// out = [h_prime (N x 128) | attention (N x N)] fp32.
//
//  k_pre    : h_t = h @ W kept in regs -> htT fp16 (transposed) + src/tgt
//             exp tables, fused in one kernel (no g_ht round trip).
//  k_bits   : adj -> packed bitmask + folded denominators (4-acc ILP).
//  k_main   : grid 288 = 96 row-tiles x 3 j-thirds, 256 thr, 2 blocks/SM;
//             8 warps x (16 rows x 128 cols); P fragments in registers
//             (fp16, 1-term MMA), B via cp.async double-buffer + ldmatrix;
//             streaming attention stores; h_prime partials to scratch.
//  k_red    : sum 3 partials -> h_prime.

#define KN    12288
#define INF_  256
#define OUTF  128
#define NWORDS (KN / 32)     // 384
#define CH    128            // K-chunk
#define NSPLIT 3
#define NCL   (KN / CH / NSPLIT)   // 32 chunks per split
#define JSPAN (KN / NSPLIT)        // 4096

__device__ __half g_htT[(size_t)OUTF * KN];
__device__ __align__(16) float g_Es[KN], g_Es2[KN], g_Etgt[KN], g_Etgt2[KN];
__device__ float g_A[KN], g_B[KN];
__device__ __align__(16) uint32_t g_bits[(size_t)KN * NWORDS];
__device__ float g_part[(size_t)NSPLIT * KN * OUTF];

// ---------------- helpers ----------------
__device__ __forceinline__ uint32_t smem_u32(const void* p) {
    uint32_t a;
    asm("{ .reg .u64 t; cvta.to.shared.u64 t, %1; cvt.u32.u64 %0, t; }" : "=r"(a) : "l"(p));
    return a;
}
__device__ __forceinline__ uint32_t packh2(float p0, float p1) {
    uint32_t r;
    asm("cvt.rn.f16x2.f32 %0, %1, %2;" : "=r"(r) : "f"(p1), "f"(p0));
    return r;
}
__device__ __forceinline__ void stcs2(float* p, float a, float b) {
    asm volatile("st.global.cs.v2.f32 [%0], {%1, %2};" :: "l"(p), "f"(a), "f"(b) : "memory");
}
__device__ __forceinline__ int4 ldcs4(const int4* p) {
    int4 v;
    asm volatile("ld.global.cs.nc.v4.s32 {%0,%1,%2,%3}, [%4];"
                 : "=r"(v.x), "=r"(v.y), "=r"(v.z), "=r"(v.w) : "l"(p));
    return v;
}

#define MMA16816(d, a0, a1, a2, a3, b0, b1) \
    asm volatile( \
        "mma.sync.aligned.m16n8k16.row.col.f32.f16.f16.f32 " \
        "{%0,%1,%2,%3}, {%4,%5,%6,%7}, {%8,%9}, {%0,%1,%2,%3};" \
        : "+f"((d).x), "+f"((d).y), "+f"((d).z), "+f"((d).w) \
        : "r"(a0), "r"(a1), "r"(a2), "r"(a3), "r"(b0), "r"(b1))

#define LDMX4(r0, r1, r2, r3, ad) \
    asm volatile("ldmatrix.sync.aligned.m8n8.x4.shared.b16 {%0,%1,%2,%3}, [%4];" \
                 : "=r"(r0), "=r"(r1), "=r"(r2), "=r"(r3) : "r"(ad))

#define CP16(dst, src) \
    asm volatile("cp.async.cg.shared.global [%0], [%1], 16;" :: "r"(dst), "l"(src) : "memory")
#define CP_COMMIT() asm volatile("cp.async.commit_group;" ::: "memory")
#define CP_WAIT1()  asm volatile("cp.async.wait_group 1;" ::: "memory")
#define CP_WAIT0()  asm volatile("cp.async.wait_group 0;" ::: "memory")

// ---------------- K1: fused h@W -> htT fp16 + exp tables ----------------
__global__ void __launch_bounds__(256) k_pre(const float* __restrict__ h,
                                             const float* __restrict__ W,
                                             const float* __restrict__ a) {
    __shared__ float h_s[8 * INF_];
    __shared__ float red[8][8];
    int t = threadIdx.x;
    int r0 = blockIdx.x * 8;
    for (int idx = t; idx < 8 * INF_; idx += 256)
        h_s[idx] = h[(size_t)r0 * INF_ + idx];
    __syncthreads();
    int c  = t & 127;
    int rg = t >> 7;
    float acc[4] = {0.f, 0.f, 0.f, 0.f};
    for (int k = 0; k < INF_; k++) {
        float w = W[k * OUTF + c];
#pragma unroll
        for (int rr = 0; rr < 4; rr++)
            acc[rr] = fmaf(h_s[(rg * 4 + rr) * INF_ + k], w, acc[rr]);
    }
    // transposed fp16 store: g_htT[c][r0 + rg*4 .. +3]
    *(uint2*)(g_htT + (size_t)c * KN + r0 + rg * 4) =
        make_uint2(packh2(acc[0], acc[1]), packh2(acc[2], acc[3]));

    // src/tgt partial sums, reduce over the 128 c-lanes (4 warps per rg)
    float av = a[c], av2 = a[OUTF + c];
    float s[8];
#pragma unroll
    for (int rr = 0; rr < 4; rr++) {
        s[rr * 2]     = acc[rr] * av;
        s[rr * 2 + 1] = acc[rr] * av2;
    }
#pragma unroll
    for (int o = 16; o > 0; o >>= 1)
#pragma unroll
        for (int i = 0; i < 8; i++)
            s[i] += __shfl_down_sync(0xFFFFFFFFu, s[i], o);
    int w = t >> 5, l = t & 31;
    if (l == 0)
#pragma unroll
        for (int i = 0; i < 8; i++) red[w][i] = s[i];
    __syncthreads();
    if (t < 16) {
        int rho = t >> 1, which = t & 1;
        int rg2 = rho >> 2, rr = rho & 3;
        float v = red[rg2 * 4 + 0][rr * 2 + which] + red[rg2 * 4 + 1][rr * 2 + which]
                + red[rg2 * 4 + 2][rr * 2 + which] + red[rg2 * 4 + 3][rr * 2 + which];
        int r = r0 + rho;
        if (which == 0) { g_Es[r]   = expf(v); g_Es2[r]   = expf(0.2f * v); }
        else            { g_Etgt[r] = expf(v); g_Etgt2[r] = expf(0.2f * v); }
    }
}

// ---------------- Kbits: bitmask + denominators (4-acc ILP) ----------------
__global__ void __launch_bounds__(256) k_bits(const int* __restrict__ adj) {
    __shared__ __align__(16) float sE1[1024], sE2[1024];
    int t = threadIdx.x;
    int l = t & 31;
    int r = blockIdx.x * 8 + (t >> 5);
    float Es = g_Es[r], Es2 = g_Es2[r];
    const int4* __restrict__ arow = (const int4*)(adj + (size_t)r * KN);
    uint32_t* __restrict__ brow = g_bits + (size_t)r * NWORDS;
    const int sh = (l & 7) * 4;
    float ls0 = 0.f, ls1 = 0.f, ls2 = 0.f, ls3 = 0.f;

    for (int jc = 0; jc < KN / 1024; jc++) {    // 12 chunks
        __syncthreads();
        *(float4*)&sE1[t * 4] = *(const float4*)(g_Etgt  + jc * 1024 + t * 4);
        *(float4*)&sE2[t * 4] = *(const float4*)(g_Etgt2 + jc * 1024 + t * 4);
        __syncthreads();
#pragma unroll
        for (int it = 0; it < 8; it++) {        // 128 j per warp per it
            int4 m = ldcs4(arow + jc * 256 + it * 32 + l);
            float4 e1 = *(const float4*)&sE1[it * 128 + l * 4];
            float4 e2 = *(const float4*)&sE2[it * 128 + l * 4];
            uint32_t nib = 0;
            if (m.x) { nib |= 1u; ls0 += fmaxf(Es * e1.x, Es2 * e2.x); }
            if (m.y) { nib |= 2u; ls1 += fmaxf(Es * e1.y, Es2 * e2.y); }
            if (m.z) { nib |= 4u; ls2 += fmaxf(Es * e1.z, Es2 * e2.z); }
            if (m.w) { nib |= 8u; ls3 += fmaxf(Es * e1.w, Es2 * e2.w); }
            uint32_t word = nib << sh;
            word |= __shfl_xor_sync(0xFFFFFFFFu, word, 1);
            word |= __shfl_xor_sync(0xFFFFFFFFu, word, 2);
            word |= __shfl_xor_sync(0xFFFFFFFFu, word, 4);
            if ((l & 7) == 0) brow[jc * 32 + it * 4 + (l >> 3)] = word;
        }
    }
    float lsum = (ls0 + ls1) + (ls2 + ls3);
#pragma unroll
    for (int o = 16; o > 0; o >>= 1) lsum += __shfl_down_sync(0xFFFFFFFFu, lsum, o);
    if (l == 0) {
        float inv = 1.0f / lsum;
        g_A[r] = Es * inv;
        g_B[r] = Es2 * inv;
    }
}

// ---------------- K2: fused P-gen + mma.sync GEMM (1-term, occ 2) --------
#define ROWSTRIDE 272
#define VERBYTES  (128 * ROWSTRIDE)   // 34816
#define SMEM_MAIN (2 * VERBYTES)      // 69632 double buffered

__global__ void __launch_bounds__(256, 2) k_main(float* __restrict__ out) {
    extern __shared__ char sm[];
    const uint32_t smb = smem_u32(sm);
    const int t  = threadIdx.x;
    const int w  = t >> 5, l = t & 31;
    const int g  = l >> 2, tq = l & 3;
    const int ti = blockIdx.x / NSPLIT;     // row tile
    const int js = blockIdx.x % NSPLIT;     // j third
    const int i0 = ti * 128;
    const int jbase = js * JSPAN;
    const int row0 = i0 + w * 16 + g;       // warp owns 16 rows
    const int row1 = row0 + 8;

    const float aA0 = g_A[row0], bB0 = g_B[row0];
    const float aA1 = g_A[row1], bB1 = g_B[row1];
    float* __restrict__ attn0 = out + (size_t)KN * OUTF + (size_t)row0 * KN;
    float* __restrict__ attn1 = out + (size_t)KN * OUTF + (size_t)row1 * KN;
    const uint4* __restrict__ bits0 = (const uint4*)(g_bits + (size_t)row0 * NWORDS) + js * NCL;
    const uint4* __restrict__ bits1 = (const uint4*)(g_bits + (size_t)row1 * NWORDS) + js * NCL;

    const int cpr = t >> 4;          // 0..15
    const int cpk = t & 15;
    const uint32_t lmrow = ((l >> 4) & 1) * 8 + (l & 7);
    const uint32_t lmoff = lmrow * ROWSTRIDE + ((l >> 3) & 1) * 16;

    float4 acc[16];
#pragma unroll
    for (int i = 0; i < 16; i++) acc[i] = make_float4(0.f, 0.f, 0.f, 0.f);

    // prologue: chunk 0 -> buf 0
#pragma unroll
    for (int i = 0; i < 8; i++) {
        int row = cpr + i * 16;
        CP16(smb + row * ROWSTRIDE + cpk * 16,
             g_htT + (size_t)row * KN + jbase + cpk * 8);
    }
    CP_COMMIT();

    for (int c = 0; c < NCL; c++) {
        const int buf = c & 1;
        if (c + 1 < NCL) {
            const int jn = jbase + (c + 1) * CH;
            const uint32_t dstb = smb + (buf ^ 1) * VERBYTES;
#pragma unroll
            for (int i = 0; i < 8; i++) {
                int row = cpr + i * 16;
                CP16(dstb + row * ROWSTRIDE + cpk * 16,
                     g_htT + (size_t)row * KN + jn + cpk * 8);
            }
            CP_COMMIT();
            CP_WAIT1();
        } else {
            CP_WAIT0();
        }
        __syncthreads();

        const uint4 w0 = bits0[c];
        const uint4 w1 = bits1[c];
        const uint32_t lmb = smb + buf * VERBYTES + lmoff;

#pragma unroll 2
        for (int kk = 0; kk < 8; kk++) {
            const int j = jbase + c * CH + kk * 16;
            float2 e1a = *(const float2*)(g_Etgt  + j + 2 * tq);
            float2 e1b = *(const float2*)(g_Etgt  + j + 2 * tq + 8);
            float2 e2a = *(const float2*)(g_Etgt2 + j + 2 * tq);
            float2 e2b = *(const float2*)(g_Etgt2 + j + 2 * tq + 8);
            const uint32_t bwa = ((const uint32_t*)&w0)[kk >> 1] >> ((kk & 1) * 16);
            const uint32_t bwb = ((const uint32_t*)&w1)[kk >> 1] >> ((kk & 1) * 16);

            float p00 = (bwa >> (2 * tq))     & 1 ? fmaxf(aA0 * e1a.x, bB0 * e2a.x) : 0.f;
            float p01 = (bwa >> (2 * tq + 1)) & 1 ? fmaxf(aA0 * e1a.y, bB0 * e2a.y) : 0.f;
            float p02 = (bwa >> (2 * tq + 8)) & 1 ? fmaxf(aA0 * e1b.x, bB0 * e2b.x) : 0.f;
            float p03 = (bwa >> (2 * tq + 9)) & 1 ? fmaxf(aA0 * e1b.y, bB0 * e2b.y) : 0.f;
            float p10 = (bwb >> (2 * tq))     & 1 ? fmaxf(aA1 * e1a.x, bB1 * e2a.x) : 0.f;
            float p11 = (bwb >> (2 * tq + 1)) & 1 ? fmaxf(aA1 * e1a.y, bB1 * e2a.y) : 0.f;
            float p12 = (bwb >> (2 * tq + 8)) & 1 ? fmaxf(aA1 * e1b.x, bB1 * e2b.x) : 0.f;
            float p13 = (bwb >> (2 * tq + 9)) & 1 ? fmaxf(aA1 * e1b.y, bB1 * e2b.y) : 0.f;

            stcs2(attn0 + j + 2 * tq,     p00, p01);
            stcs2(attn0 + j + 2 * tq + 8, p02, p03);
            stcs2(attn1 + j + 2 * tq,     p10, p11);
            stcs2(attn1 + j + 2 * tq + 8, p12, p13);

            const uint32_t ah0 = packh2(p00, p01);
            const uint32_t ah1 = packh2(p10, p11);
            const uint32_t ah2 = packh2(p02, p03);
            const uint32_t ah3 = packh2(p12, p13);

            const uint32_t lmk = lmb + kk * 32;
#pragma unroll
            for (int np = 0; np < 8; np++) {
                uint32_t bh0, bh1, bh2, bh3;
                LDMX4(bh0, bh1, bh2, bh3, lmk + np * (16 * ROWSTRIDE));
                MMA16816(acc[2 * np],     ah0, ah1, ah2, ah3, bh0, bh1);
                MMA16816(acc[2 * np + 1], ah0, ah1, ah2, ah3, bh2, bh3);
            }
        }
        __syncthreads();
    }

    // epilogue: h_prime partial for this j-third
    float* __restrict__ part = g_part + (size_t)js * KN * OUTF;
#pragma unroll
    for (int nt = 0; nt < 16; nt++) {
        int cc = nt * 8 + 2 * tq;
        *(float2*)(part + (size_t)row0 * OUTF + cc) = make_float2(acc[nt].x, acc[nt].y);
        *(float2*)(part + (size_t)row1 * OUTF + cc) = make_float2(acc[nt].z, acc[nt].w);
    }
}

// ---------------- K3: reduce partials ----------------
__global__ void __launch_bounds__(256) k_red(float* __restrict__ out) {
    const size_t SZ = (size_t)KN * OUTF;
    size_t idx = ((size_t)blockIdx.x * 256 + threadIdx.x) * 4;
    float4 a = *(const float4*)(g_part + idx);
    float4 b = *(const float4*)(g_part + SZ + idx);
    float4 c = *(const float4*)(g_part + 2 * SZ + idx);
    *(float4*)(out + idx) = make_float4(a.x + b.x + c.x, a.y + b.y + c.y,
                                        a.z + b.z + c.z, a.w + b.w + c.w);
}

extern "C" void kernel_launch(void* const* d_in, const int* in_sizes, int n_in,
                              void* d_out, int out_size) {
    const float* h   = (const float*)d_in[0];
    const int*   adj = (const int*)d_in[1];
    const float* W   = (const float*)d_in[2];
    const float* a   = (const float*)d_in[3];
    float* out = (float*)d_out;

    cudaFuncSetAttribute(k_main, cudaFuncAttributeMaxDynamicSharedMemorySize, SMEM_MAIN);

    k_pre<<<KN / 8, 256>>>(h, W, a);
    k_bits<<<KN / 8, 256>>>(adj);
    k_main<<<(KN / 128) * NSPLIT, 256, SMEM_MAIN>>>(out);
    k_red<<<(KN * OUTF) / (256 * 4), 256>>>(out);
}